// round 1
// baseline (speedup 1.0000x reference)
#include <cuda_runtime.h>
#include <math.h>

#define B_  2
#define L_  2048
#define D_  1024
#define H_  16
#define HD_ 64
#define ROWS_ (B_*L_)          // 4096
#define EPS_ 1e-6f

// ---------------- scratch (no allocations allowed) ----------------
__device__ float g_cp [ROWS_*3*D_];   // cond proj: (row, d*3+comp)
__device__ float g_xm [ROWS_*D_];     // modulated normed x
__device__ float g_qkv[ROWS_*3*D_];   // qkv proj
__device__ float g_q  [ROWS_*D_];     // (b,h,l,hd), q pre-scaled by 1/8
__device__ float g_k  [ROWS_*D_];
__device__ float g_v  [ROWS_*D_];
__device__ float g_ao [ROWS_*D_];     // attention output (b,l, h*64+hd)

// ---------------- 128x128x8 fp32 GEMM, optional fused epilogue ----------------
// C[M,N] = A[M,K] @ B[K,N]; EPI=1: += resid[row,col] + cp[row, col*3+2] (gate)
template<int EPI>
__global__ void sgemm128(const float* __restrict__ A, const float* __restrict__ Bm,
                         float* __restrict__ C, int M, int N, int K,
                         const float* __restrict__ resid, const float* __restrict__ cp)
{
    __shared__ float As[8][128];
    __shared__ float Bs[8][128];
    const int tid = threadIdx.x;
    const int tx = tid & 15, ty = tid >> 4;
    const int bm = blockIdx.y * 128, bn = blockIdx.x * 128;
    const int arow = tid >> 1;          // 0..127
    const int acol = (tid & 1) * 4;     // 0 or 4
    const int brow = tid >> 5;          // 0..7
    const int bcol = (tid & 31) * 4;    // 0..124

    float acc[8][8];
#pragma unroll
    for (int i = 0; i < 8; i++)
#pragma unroll
        for (int j = 0; j < 8; j++) acc[i][j] = 0.f;

    const float* Ap = A  + (size_t)(bm + arow) * K + acol;
    const float* Bp = Bm + (size_t)brow * N + bn + bcol;

    for (int k0 = 0; k0 < K; k0 += 8) {
        float4 av = *(const float4*)(Ap + k0);
        float4 bv = *(const float4*)(Bp + (size_t)k0 * N);
        As[acol+0][arow] = av.x; As[acol+1][arow] = av.y;
        As[acol+2][arow] = av.z; As[acol+3][arow] = av.w;
        *(float4*)&Bs[brow][bcol] = bv;
        __syncthreads();
#pragma unroll
        for (int kk = 0; kk < 8; kk++) {
            float a[8], b[8];
            *(float4*)(a)   = *(const float4*)&As[kk][ty*8];
            *(float4*)(a+4) = *(const float4*)&As[kk][ty*8+4];
            *(float4*)(b)   = *(const float4*)&Bs[kk][tx*8];
            *(float4*)(b+4) = *(const float4*)&Bs[kk][tx*8+4];
#pragma unroll
            for (int i = 0; i < 8; i++)
#pragma unroll
                for (int j = 0; j < 8; j++)
                    acc[i][j] = fmaf(a[i], b[j], acc[i][j]);
        }
        __syncthreads();
    }

#pragma unroll
    for (int i = 0; i < 8; i++) {
        const int row = bm + ty*8 + i;
#pragma unroll
        for (int j = 0; j < 8; j++) {
            const int col = bn + tx*8 + j;
            float v = acc[i][j];
            if (EPI == 1)
                v += resid[(size_t)row*N + col] + cp[(size_t)row*(3*D_) + col*3 + 2];
            C[(size_t)row*N + col] = v;
        }
    }
}

// ---------------- RMSNorm + AdaLN modulation ----------------
__global__ void modulate_kernel(const float* __restrict__ x,
                                const float* __restrict__ rms_scale,
                                const float* __restrict__ cp,
                                float* __restrict__ xm)
{
    const int row = blockIdx.x;
    const int tid = threadIdx.x;
    const float* xr = x + (size_t)row * D_;
    __shared__ float red[256];
    float s = 0.f;
    for (int d = tid; d < D_; d += 256) { float v = xr[d]; s += v*v; }
    red[tid] = s; __syncthreads();
    for (int o = 128; o > 0; o >>= 1) {
        if (tid < o) red[tid] += red[tid + o];
        __syncthreads();
    }
    const float rn = rsqrtf(red[0] / (float)D_ + EPS_);
    for (int d = tid; d < D_; d += 256) {
        const float scale = cp[(size_t)row*(3*D_) + 3*d    ];
        const float shift = cp[(size_t)row*(3*D_) + 3*d + 1];
        xm[(size_t)row*D_ + d] = xr[d]*rn*rms_scale[d]*(1.f + scale) + shift;
    }
}

// ---------------- RoPE + head split ----------------
// qkv layout: [row, e*3 + comp], e = hd*H + h. Output layout (b,h,l,hd).
__global__ void rope_split_kernel(const float* __restrict__ qkv,
                                  const float* __restrict__ pos,
                                  float* __restrict__ q, float* __restrict__ k,
                                  float* __restrict__ v)
{
    const int row = blockIdx.x;          // b*L + l
    const int b = row / L_, l = row % L_;
    const int tid = threadIdx.x;
    const float* qr = qkv + (size_t)row * 3 * D_;
    const float* pr = pos + (size_t)row * 2 * HD_;
    for (int e = tid; e < D_; e += 256) {
        const int h  = e & (H_-1);
        const int hd = e >> 4;           // e / H_
        const float qv = qr[3*e + 0];
        const float kv = qr[3*e + 1];
        const float vv = qr[3*e + 2];
        const int hd2 = (hd < 32) ? hd + 32 : hd - 32;
        const int e2  = hd2 * H_ + h;
        const float sgn = (hd < 32) ? -1.f : 1.f;
        const float q2 = qr[3*e2 + 0];
        const float k2 = qr[3*e2 + 1];
        const float sn = pr[2*hd];
        const float cs = pr[2*hd + 1];
        const size_t o = ((size_t)(b*H_ + h)*L_ + l)*HD_ + hd;
        q[o] = (qv*cs + sgn*q2*sn) * 0.125f;   // 1/sqrt(64) folded into q
        k[o] =  kv*cs + sgn*k2*sn;
        v[o] =  vv;
    }
}

// ---------------- attention: 64-row flash tiles, full (non-causal) ----------------
// grid (L/64, B*H), 256 threads (16x16), each thread owns 4x4 of S/P and O.
__global__ void attn_kernel(const float* __restrict__ q, const float* __restrict__ k,
                            const float* __restrict__ v, float* __restrict__ out)
{
    extern __shared__ float sm[];
    float* sQ  = sm;                 // [64][65]
    float* sKP = sm + 64*65;         // [64][65]  K tile, then reused for P
    float* sV  = sm + 2*64*65;       // [64][65]

    const int qt = blockIdx.x;
    const int bh = blockIdx.y;
    const int b = bh / H_, h = bh % H_;
    const int tid = threadIdx.x;
    const int tx = tid & 15, ty = tid >> 4;
    const int r0 = ty*4, c0 = tx*4;

    const float* qb = q + ((size_t)bh*L_ + qt*64)*HD_;
    const float* kb = k + (size_t)bh*L_*HD_;
    const float* vb = v + (size_t)bh*L_*HD_;

    // load Q tile
    for (int t = tid; t < 64*16; t += 256) {
        const int r = t >> 4, c4 = (t & 15) * 4;
        float4 qv = *(const float4*)(qb + r*64 + c4);
        sQ[r*65+c4+0]=qv.x; sQ[r*65+c4+1]=qv.y; sQ[r*65+c4+2]=qv.z; sQ[r*65+c4+3]=qv.w;
    }

    float m_i[4], l_i[4], o[4][4];
#pragma unroll
    for (int i = 0; i < 4; i++) {
        m_i[i] = -INFINITY; l_i[i] = 0.f;
#pragma unroll
        for (int j = 0; j < 4; j++) o[i][j] = 0.f;
    }

    for (int n0 = 0; n0 < L_; n0 += 64) {
        __syncthreads();   // protect prior-iteration P/V reads & first-iter Q
        // load K and V tiles
        for (int t = tid; t < 64*16; t += 256) {
            const int r = t >> 4, c4 = (t & 15) * 4;
            float4 kv = *(const float4*)(kb + (size_t)(n0+r)*64 + c4);
            sKP[r*65+c4+0]=kv.x; sKP[r*65+c4+1]=kv.y; sKP[r*65+c4+2]=kv.z; sKP[r*65+c4+3]=kv.w;
            float4 vv = *(const float4*)(vb + (size_t)(n0+r)*64 + c4);
            sV [r*65+c4+0]=vv.x; sV [r*65+c4+1]=vv.y; sV [r*65+c4+2]=vv.z; sV [r*65+c4+3]=vv.w;
        }
        __syncthreads();

        // S = Q K^T (4x4 per thread)
        float s[4][4];
#pragma unroll
        for (int i = 0; i < 4; i++)
#pragma unroll
            for (int j = 0; j < 4; j++) s[i][j] = 0.f;
#pragma unroll 4
        for (int d = 0; d < 64; d++) {
            float qa[4], kk[4];
#pragma unroll
            for (int i = 0; i < 4; i++) qa[i] = sQ [(r0+i)*65 + d];
#pragma unroll
            for (int j = 0; j < 4; j++) kk[j] = sKP[(c0+j)*65 + d];
#pragma unroll
            for (int i = 0; i < 4; i++)
#pragma unroll
                for (int j = 0; j < 4; j++)
                    s[i][j] = fmaf(qa[i], kk[j], s[i][j]);
        }

        // online softmax (row = 16 lanes sharing ty)
#pragma unroll
        for (int i = 0; i < 4; i++) {
            float mx = s[i][0];
#pragma unroll
            for (int j = 1; j < 4; j++) mx = fmaxf(mx, s[i][j]);
#pragma unroll
            for (int off = 1; off < 16; off <<= 1)
                mx = fmaxf(mx, __shfl_xor_sync(0xffffffffu, mx, off));
            const float m_new = fmaxf(m_i[i], mx);
            const float corr = __expf(m_i[i] - m_new);
            float rs = 0.f;
#pragma unroll
            for (int j = 0; j < 4; j++) { s[i][j] = __expf(s[i][j] - m_new); rs += s[i][j]; }
#pragma unroll
            for (int off = 1; off < 16; off <<= 1)
                rs += __shfl_xor_sync(0xffffffffu, rs, off);
            l_i[i] = l_i[i]*corr + rs;
            m_i[i] = m_new;
#pragma unroll
            for (int j = 0; j < 4; j++) o[i][j] *= corr;
        }

        __syncthreads();   // everyone done reading K
        // stage P into sKP
#pragma unroll
        for (int i = 0; i < 4; i++)
#pragma unroll
            for (int j = 0; j < 4; j++) sKP[(r0+i)*65 + c0 + j] = s[i][j];
        __syncthreads();

        // O += P V
#pragma unroll 4
        for (int c = 0; c < 64; c++) {
            float pv[4], vv[4];
#pragma unroll
            for (int i = 0; i < 4; i++) pv[i] = sKP[(r0+i)*65 + c];
#pragma unroll
            for (int j = 0; j < 4; j++) vv[j] = sV [c*65 + c0 + j];
#pragma unroll
            for (int i = 0; i < 4; i++)
#pragma unroll
                for (int j = 0; j < 4; j++)
                    o[i][j] = fmaf(pv[i], vv[j], o[i][j]);
        }
    }

    // write out: (b, l, h*64+hd)
#pragma unroll
    for (int i = 0; i < 4; i++) {
        const float inv = 1.f / l_i[i];
        const int l = qt*64 + r0 + i;
#pragma unroll
        for (int j = 0; j < 4; j++)
            out[((size_t)(b*L_ + l))*D_ + h*64 + c0 + j] = o[i][j] * inv;
    }
}

// ---------------- launch ----------------
extern "C" void kernel_launch(void* const* d_in, const int* in_sizes, int n_in,
                              void* d_out, int out_size)
{
    const float* x         = (const float*)d_in[0];
    const float* cond      = (const float*)d_in[1];
    const float* pos       = (const float*)d_in[2];
    const float* rms_scale = (const float*)d_in[3];
    const float* W_cond    = (const float*)d_in[4];
    const float* W_qkv     = (const float*)d_in[5];
    const float* W_out     = (const float*)d_in[6];
    float* out = (float*)d_out;

    float *cp, *xm, *qkv, *qb, *kb, *vb, *ao;
    cudaGetSymbolAddress((void**)&cp,  g_cp);
    cudaGetSymbolAddress((void**)&xm,  g_xm);
    cudaGetSymbolAddress((void**)&qkv, g_qkv);
    cudaGetSymbolAddress((void**)&qb,  g_q);
    cudaGetSymbolAddress((void**)&kb,  g_k);
    cudaGetSymbolAddress((void**)&vb,  g_v);
    cudaGetSymbolAddress((void**)&ao,  g_ao);

    const int smem_attn = 3 * 64 * 65 * (int)sizeof(float);   // 49,920 B
    cudaFuncSetAttribute(attn_kernel, cudaFuncAttributeMaxDynamicSharedMemorySize, smem_attn);

    // 1) cond projection -> scale/shift/gate
    {
        dim3 g(3*D_/128, ROWS_/128);
        sgemm128<0><<<g, 256>>>(cond, W_cond, cp, ROWS_, 3*D_, D_, nullptr, nullptr);
    }
    // 2) RMSNorm + modulation
    modulate_kernel<<<ROWS_, 256>>>(x, rms_scale, cp, xm);
    // 3) QKV projection
    {
        dim3 g(3*D_/128, ROWS_/128);
        sgemm128<0><<<g, 256>>>(xm, W_qkv, qkv, ROWS_, 3*D_, D_, nullptr, nullptr);
    }
    // 4) RoPE + head split
    rope_split_kernel<<<ROWS_, 256>>>(qkv, pos, qb, kb, vb);
    // 5) attention
    {
        dim3 g(L_/64, B_*H_);
        attn_kernel<<<g, 256, smem_attn>>>(qb, kb, vb, ao);
    }
    // 6) output projection + residual + gate
    {
        dim3 g(D_/128, ROWS_/128);
        sgemm128<1><<<g, 256>>>(ao, W_out, out, ROWS_, D_, D_, x, cp);
    }
}

// round 4
// speedup vs baseline: 1.1995x; 1.1995x over previous
#include <cuda_runtime.h>
#include <stdint.h>
#include <math.h>

#define B_  2
#define L_  2048
#define D_  1024
#define H_  16
#define HD_ 64
#define ROWS_ (B_*L_)          // 4096
#define EPS_ 1e-6f

// ---------------- scratch (no allocations allowed) ----------------
__device__ float g_cp [ROWS_*3*D_];   // cond proj: (row, d*3+comp)
__device__ float g_xm [ROWS_*D_];     // modulated normed x
__device__ float g_qkv[ROWS_*3*D_];   // qkv proj
__device__ float g_q  [ROWS_*D_];     // (b,h,l,hd), q pre-scaled by 1/8
__device__ float g_k  [ROWS_*D_];
__device__ float g_v  [ROWS_*D_];
__device__ float g_ao [ROWS_*D_];     // attention output (b,l, h*64+hd)

// ---------------- tf32 helpers ----------------
__device__ __forceinline__ uint32_t f2tf32(float f) {
    uint32_t r;
    asm("cvt.rna.tf32.f32 %0, %1;" : "=r"(r) : "f"(f));
    return r;
}

__device__ __forceinline__ void mma_tf32(float* c, const uint32_t* a, const uint32_t* b) {
    asm volatile(
        "mma.sync.aligned.m16n8k8.row.col.f32.tf32.tf32.f32 "
        "{%0,%1,%2,%3}, {%4,%5,%6,%7}, {%8,%9}, {%0,%1,%2,%3};"
        : "+f"(c[0]), "+f"(c[1]), "+f"(c[2]), "+f"(c[3])
        : "r"(a[0]), "r"(a[1]), "r"(a[2]), "r"(a[3]), "r"(b[0]), "r"(b[1]));
}

// ---------------- tf32 tensor-core GEMM: 128x128 tile, BK=16 ----------------
// C[M,N] = A[M,K] @ B[K,N], row-major. EPI=1: += resid[row,col] + cp[row,col*3+2]
// 256 threads = 8 warps in 2(M) x 4(N); warp tile 64x32 = 4x4 frags of m16n8k8.
template<int EPI>
__global__ void gemm_tf32(const float* __restrict__ A, const float* __restrict__ Bm,
                          float* __restrict__ C, int M, int N, int K,
                          const float* __restrict__ resid, const float* __restrict__ cp)
{
    __shared__ float As[128][20];   // [m][k], pad to 20 -> conflict-free frag loads
    __shared__ float Bs[128][20];   // [n][k] (B transposed on store)

    const int tid  = threadIdx.x;
    const int lane = tid & 31;
    const int warp = tid >> 5;
    const int wm = warp & 1;        // 0..1  (64-row slab)
    const int wn = warp >> 1;       // 0..3  (32-col slab)
    const int bm = blockIdx.y * 128, bn = blockIdx.x * 128;
    const int g = lane >> 2;        // groupID 0..7
    const int t = lane & 3;         // thread-in-group 0..3

    float acc[4][4][4];
#pragma unroll
    for (int i = 0; i < 4; i++)
#pragma unroll
        for (int j = 0; j < 4; j++)
#pragma unroll
            for (int e = 0; e < 4; e++) acc[i][j][e] = 0.f;

    float4 ra[2], rb[2];
    auto loadg = [&](int k0) {
#pragma unroll
        for (int i = 0; i < 2; i++) {
            const int idx = tid * 2 + i;
            ra[i] = *(const float4*)(A  + (size_t)(bm + (idx >> 2)) * K + k0 + (idx & 3) * 4);
            rb[i] = *(const float4*)(Bm + (size_t)(k0 + (idx >> 5)) * N + bn + (idx & 31) * 4);
        }
    };
    auto stores = [&]() {
#pragma unroll
        for (int i = 0; i < 2; i++) {
            const int idx = tid * 2 + i;
            const int ar = idx >> 2, ac = (idx & 3) * 4;
            As[ar][ac+0] = __uint_as_float(f2tf32(ra[i].x));
            As[ar][ac+1] = __uint_as_float(f2tf32(ra[i].y));
            As[ar][ac+2] = __uint_as_float(f2tf32(ra[i].z));
            As[ar][ac+3] = __uint_as_float(f2tf32(ra[i].w));
            const int bk = idx >> 5, bc = (idx & 31) * 4;
            Bs[bc+0][bk] = __uint_as_float(f2tf32(rb[i].x));
            Bs[bc+1][bk] = __uint_as_float(f2tf32(rb[i].y));
            Bs[bc+2][bk] = __uint_as_float(f2tf32(rb[i].z));
            Bs[bc+3][bk] = __uint_as_float(f2tf32(rb[i].w));
        }
    };

    const int kTiles = K / 16;
    loadg(0);
    stores();
    __syncthreads();

    for (int kt = 0; kt < kTiles; kt++) {
        if (kt + 1 < kTiles) loadg((kt + 1) * 16);
#pragma unroll
        for (int k8 = 0; k8 < 16; k8 += 8) {
            uint32_t af[4][4], bf[4][2];
#pragma unroll
            for (int i = 0; i < 4; i++) {
                const int mb = wm * 64 + i * 16;
                af[i][0] = __float_as_uint(As[mb + g    ][k8 + t    ]);
                af[i][1] = __float_as_uint(As[mb + g + 8][k8 + t    ]);
                af[i][2] = __float_as_uint(As[mb + g    ][k8 + t + 4]);
                af[i][3] = __float_as_uint(As[mb + g + 8][k8 + t + 4]);
            }
#pragma unroll
            for (int j = 0; j < 4; j++) {
                const int nb = wn * 32 + j * 8;
                bf[j][0] = __float_as_uint(Bs[nb + g][k8 + t    ]);
                bf[j][1] = __float_as_uint(Bs[nb + g][k8 + t + 4]);
            }
#pragma unroll
            for (int i = 0; i < 4; i++)
#pragma unroll
                for (int j = 0; j < 4; j++)
                    mma_tf32(acc[i][j], af[i], bf[j]);
        }
        __syncthreads();
        if (kt + 1 < kTiles) {
            stores();
            __syncthreads();
        }
    }

    // epilogue: c0,c1 at (row, col), (row, col+1); c2,c3 at row+8
#pragma unroll
    for (int i = 0; i < 4; i++) {
#pragma unroll
        for (int j = 0; j < 4; j++) {
            const int r = bm + wm * 64 + i * 16 + g;
            const int c = bn + wn * 32 + j * 8 + t * 2;
            float v0 = acc[i][j][0], v1 = acc[i][j][1];
            float v2 = acc[i][j][2], v3 = acc[i][j][3];
            if (EPI == 1) {
                v0 += resid[(size_t)r*N + c]       + cp[(size_t)r*(3*D_) + c*3 + 2];
                v1 += resid[(size_t)r*N + c + 1]   + cp[(size_t)r*(3*D_) + (c+1)*3 + 2];
                v2 += resid[(size_t)(r+8)*N + c]   + cp[(size_t)(r+8)*(3*D_) + c*3 + 2];
                v3 += resid[(size_t)(r+8)*N + c+1] + cp[(size_t)(r+8)*(3*D_) + (c+1)*3 + 2];
            }
            C[(size_t)r*N + c]         = v0;
            C[(size_t)r*N + c + 1]     = v1;
            C[(size_t)(r+8)*N + c]     = v2;
            C[(size_t)(r+8)*N + c + 1] = v3;
        }
    }
}

// ---------------- RMSNorm + AdaLN modulation ----------------
__global__ void modulate_kernel(const float* __restrict__ x,
                                const float* __restrict__ rms_scale,
                                const float* __restrict__ cp,
                                float* __restrict__ xm)
{
    const int row = blockIdx.x;
    const int tid = threadIdx.x;
    const float* xr = x + (size_t)row * D_;
    __shared__ float red[256];
    float s = 0.f;
    for (int d = tid; d < D_; d += 256) { float v = xr[d]; s += v*v; }
    red[tid] = s; __syncthreads();
    for (int o = 128; o > 0; o >>= 1) {
        if (tid < o) red[tid] += red[tid + o];
        __syncthreads();
    }
    const float rn = rsqrtf(red[0] / (float)D_ + EPS_);
    for (int d = tid; d < D_; d += 256) {
        const float scale = cp[(size_t)row*(3*D_) + 3*d    ];
        const float shift = cp[(size_t)row*(3*D_) + 3*d + 1];
        xm[(size_t)row*D_ + d] = xr[d]*rn*rms_scale[d]*(1.f + scale) + shift;
    }
}

// ---------------- RoPE + head split ----------------
__global__ void rope_split_kernel(const float* __restrict__ qkv,
                                  const float* __restrict__ pos,
                                  float* __restrict__ q, float* __restrict__ k,
                                  float* __restrict__ v)
{
    const int row = blockIdx.x;          // b*L + l
    const int b = row / L_, l = row % L_;
    const int tid = threadIdx.x;
    const float* qr = qkv + (size_t)row * 3 * D_;
    const float* pr = pos + (size_t)row * 2 * HD_;
    for (int e = tid; e < D_; e += 256) {
        const int h  = e & (H_-1);
        const int hd = e >> 4;
        const float qv = qr[3*e + 0];
        const float kv = qr[3*e + 1];
        const float vv = qr[3*e + 2];
        const int hd2 = (hd < 32) ? hd + 32 : hd - 32;
        const int e2  = hd2 * H_ + h;
        const float sgn = (hd < 32) ? -1.f : 1.f;
        const float q2 = qr[3*e2 + 0];
        const float k2 = qr[3*e2 + 1];
        const float sn = pr[2*hd];
        const float cs = pr[2*hd + 1];
        const size_t o = ((size_t)(b*H_ + h)*L_ + l)*HD_ + hd;
        q[o] = (qv*cs + sgn*q2*sn) * 0.125f;
        k[o] =  kv*cs + sgn*k2*sn;
        v[o] =  vv;
    }
}

// ---------------- attention: 64-row flash tiles (fp32) ----------------
__global__ void attn_kernel(const float* __restrict__ q, const float* __restrict__ k,
                            const float* __restrict__ v, float* __restrict__ out)
{
    extern __shared__ float sm[];
    float* sQ  = sm;
    float* sKP = sm + 64*65;
    float* sV  = sm + 2*64*65;

    const int qt = blockIdx.x;
    const int bh = blockIdx.y;
    const int b = bh / H_, h = bh % H_;
    const int tid = threadIdx.x;
    const int tx = tid & 15, ty = tid >> 4;
    const int r0 = ty*4, c0 = tx*4;

    const float* qb = q + ((size_t)bh*L_ + qt*64)*HD_;
    const float* kb = k + (size_t)bh*L_*HD_;
    const float* vb = v + (size_t)bh*L_*HD_;

    for (int t = tid; t < 64*16; t += 256) {
        const int r = t >> 4, c4 = (t & 15) * 4;
        float4 qv = *(const float4*)(qb + r*64 + c4);
        sQ[r*65+c4+0]=qv.x; sQ[r*65+c4+1]=qv.y; sQ[r*65+c4+2]=qv.z; sQ[r*65+c4+3]=qv.w;
    }

    float m_i[4], l_i[4], o[4][4];
#pragma unroll
    for (int i = 0; i < 4; i++) {
        m_i[i] = -INFINITY; l_i[i] = 0.f;
#pragma unroll
        for (int j = 0; j < 4; j++) o[i][j] = 0.f;
    }

    for (int n0 = 0; n0 < L_; n0 += 64) {
        __syncthreads();
        for (int t = tid; t < 64*16; t += 256) {
            const int r = t >> 4, c4 = (t & 15) * 4;
            float4 kv = *(const float4*)(kb + (size_t)(n0+r)*64 + c4);
            sKP[r*65+c4+0]=kv.x; sKP[r*65+c4+1]=kv.y; sKP[r*65+c4+2]=kv.z; sKP[r*65+c4+3]=kv.w;
            float4 vv = *(const float4*)(vb + (size_t)(n0+r)*64 + c4);
            sV [r*65+c4+0]=vv.x; sV [r*65+c4+1]=vv.y; sV [r*65+c4+2]=vv.z; sV [r*65+c4+3]=vv.w;
        }
        __syncthreads();

        float s[4][4];
#pragma unroll
        for (int i = 0; i < 4; i++)
#pragma unroll
            for (int j = 0; j < 4; j++) s[i][j] = 0.f;
#pragma unroll 4
        for (int d = 0; d < 64; d++) {
            float qa[4], kk[4];
#pragma unroll
            for (int i = 0; i < 4; i++) qa[i] = sQ [(r0+i)*65 + d];
#pragma unroll
            for (int j = 0; j < 4; j++) kk[j] = sKP[(c0+j)*65 + d];
#pragma unroll
            for (int i = 0; i < 4; i++)
#pragma unroll
                for (int j = 0; j < 4; j++)
                    s[i][j] = fmaf(qa[i], kk[j], s[i][j]);
        }

#pragma unroll
        for (int i = 0; i < 4; i++) {
            float mx = s[i][0];
#pragma unroll
            for (int j = 1; j < 4; j++) mx = fmaxf(mx, s[i][j]);
#pragma unroll
            for (int off = 1; off < 16; off <<= 1)
                mx = fmaxf(mx, __shfl_xor_sync(0xffffffffu, mx, off));
            const float m_new = fmaxf(m_i[i], mx);
            const float corr = __expf(m_i[i] - m_new);
            float rs = 0.f;
#pragma unroll
            for (int j = 0; j < 4; j++) { s[i][j] = __expf(s[i][j] - m_new); rs += s[i][j]; }
#pragma unroll
            for (int off = 1; off < 16; off <<= 1)
                rs += __shfl_xor_sync(0xffffffffu, rs, off);
            l_i[i] = l_i[i]*corr + rs;
            m_i[i] = m_new;
#pragma unroll
            for (int j = 0; j < 4; j++) o[i][j] *= corr;
        }

        __syncthreads();
#pragma unroll
        for (int i = 0; i < 4; i++)
#pragma unroll
            for (int j = 0; j < 4; j++) sKP[(r0+i)*65 + c0 + j] = s[i][j];
        __syncthreads();

#pragma unroll 4
        for (int c = 0; c < 64; c++) {
            float pv[4], vv[4];
#pragma unroll
            for (int i = 0; i < 4; i++) pv[i] = sKP[(r0+i)*65 + c];
#pragma unroll
            for (int j = 0; j < 4; j++) vv[j] = sV [c*65 + c0 + j];
#pragma unroll
            for (int i = 0; i < 4; i++)
#pragma unroll
                for (int j = 0; j < 4; j++)
                    o[i][j] = fmaf(pv[i], vv[j], o[i][j]);
        }
    }

#pragma unroll
    for (int i = 0; i < 4; i++) {
        const float inv = 1.f / l_i[i];
        const int l = qt*64 + r0 + i;
#pragma unroll
        for (int j = 0; j < 4; j++)
            out[((size_t)(b*L_ + l))*D_ + h*64 + c0 + j] = o[i][j] * inv;
    }
}

// ---------------- launch ----------------
extern "C" void kernel_launch(void* const* d_in, const int* in_sizes, int n_in,
                              void* d_out, int out_size)
{
    const float* x         = (const float*)d_in[0];
    const float* cond      = (const float*)d_in[1];
    const float* pos       = (const float*)d_in[2];
    const float* rms_scale = (const float*)d_in[3];
    const float* W_cond    = (const float*)d_in[4];
    const float* W_qkv     = (const float*)d_in[5];
    const float* W_out     = (const float*)d_in[6];
    float* out = (float*)d_out;

    float *cp, *xm, *qkv, *qb, *kb, *vb, *ao;
    cudaGetSymbolAddress((void**)&cp,  g_cp);
    cudaGetSymbolAddress((void**)&xm,  g_xm);
    cudaGetSymbolAddress((void**)&qkv, g_qkv);
    cudaGetSymbolAddress((void**)&qb,  g_q);
    cudaGetSymbolAddress((void**)&kb,  g_k);
    cudaGetSymbolAddress((void**)&vb,  g_v);
    cudaGetSymbolAddress((void**)&ao,  g_ao);

    const int smem_attn = 3 * 64 * 65 * (int)sizeof(float);
    cudaFuncSetAttribute(attn_kernel, cudaFuncAttributeMaxDynamicSharedMemorySize, smem_attn);

    // 1) cond projection
    {
        dim3 g(3*D_/128, ROWS_/128);
        gemm_tf32<0><<<g, 256>>>(cond, W_cond, cp, ROWS_, 3*D_, D_, nullptr, nullptr);
    }
    // 2) RMSNorm + modulation
    modulate_kernel<<<ROWS_, 256>>>(x, rms_scale, cp, xm);
    // 3) QKV projection
    {
        dim3 g(3*D_/128, ROWS_/128);
        gemm_tf32<0><<<g, 256>>>(xm, W_qkv, qkv, ROWS_, 3*D_, D_, nullptr, nullptr);
    }
    // 4) RoPE + head split
    rope_split_kernel<<<ROWS_, 256>>>(qkv, pos, qb, kb, vb);
    // 5) attention
    {
        dim3 g(L_/64, B_*H_);
        attn_kernel<<<g, 256, smem_attn>>>(qb, kb, vb, ao);
    }
    // 6) output projection + residual + gate
    {
        dim3 g(D_/128, ROWS_/128);
        gemm_tf32<1><<<g, 256>>>(ao, W_out, out, ROWS_, D_, D_, x, cp);
    }
}

// round 5
// speedup vs baseline: 1.8923x; 1.5776x over previous
#include <cuda_runtime.h>
#include <stdint.h>
#include <math.h>

#define B_  2
#define L_  2048
#define D_  1024
#define H_  16
#define HD_ 64
#define ROWS_ (B_*L_)          // 4096
#define EPS_ 1e-6f

// ---------------- scratch (no allocations allowed) ----------------
__device__ float g_cp [ROWS_*3*D_];   // cond proj: (row, d*3+comp)
__device__ float g_xm [ROWS_*D_];     // modulated normed x
__device__ float g_qkv[ROWS_*3*D_];   // qkv proj
__device__ float g_q  [ROWS_*D_];     // (b,h,l,hd), q pre-scaled by 1/8
__device__ float g_k  [ROWS_*D_];
__device__ float g_v  [ROWS_*D_];
__device__ float g_ao [ROWS_*D_];     // attention output (b,l, h*64+hd)

// ---------------- tf32 helpers ----------------
__device__ __forceinline__ uint32_t f2tf32(float f) {
    uint32_t r;
    asm("cvt.rna.tf32.f32 %0, %1;" : "=r"(r) : "f"(f));
    return r;
}

__device__ __forceinline__ void mma_tf32(float* c, const uint32_t* a, const uint32_t* b) {
    asm volatile(
        "mma.sync.aligned.m16n8k8.row.col.f32.tf32.tf32.f32 "
        "{%0,%1,%2,%3}, {%4,%5,%6,%7}, {%8,%9}, {%0,%1,%2,%3};"
        : "+f"(c[0]), "+f"(c[1]), "+f"(c[2]), "+f"(c[3])
        : "r"(a[0]), "r"(a[1]), "r"(a[2]), "r"(a[3]), "r"(b[0]), "r"(b[1]));
}

// ---------------- tf32 tensor-core GEMM: 128x128 tile, BK=16 ----------------
template<int EPI>
__global__ void gemm_tf32(const float* __restrict__ A, const float* __restrict__ Bm,
                          float* __restrict__ C, int M, int N, int K,
                          const float* __restrict__ resid, const float* __restrict__ cp)
{
    __shared__ float As[128][20];
    __shared__ float Bs[128][20];

    const int tid  = threadIdx.x;
    const int lane = tid & 31;
    const int warp = tid >> 5;
    const int wm = warp & 1;
    const int wn = warp >> 1;
    const int bm = blockIdx.y * 128, bn = blockIdx.x * 128;
    const int g = lane >> 2;
    const int t = lane & 3;

    float acc[4][4][4];
#pragma unroll
    for (int i = 0; i < 4; i++)
#pragma unroll
        for (int j = 0; j < 4; j++)
#pragma unroll
            for (int e = 0; e < 4; e++) acc[i][j][e] = 0.f;

    float4 ra[2], rb[2];
    auto loadg = [&](int k0) {
#pragma unroll
        for (int i = 0; i < 2; i++) {
            const int idx = tid * 2 + i;
            ra[i] = *(const float4*)(A  + (size_t)(bm + (idx >> 2)) * K + k0 + (idx & 3) * 4);
            rb[i] = *(const float4*)(Bm + (size_t)(k0 + (idx >> 5)) * N + bn + (idx & 31) * 4);
        }
    };
    auto stores = [&]() {
#pragma unroll
        for (int i = 0; i < 2; i++) {
            const int idx = tid * 2 + i;
            const int ar = idx >> 2, ac = (idx & 3) * 4;
            As[ar][ac+0] = __uint_as_float(f2tf32(ra[i].x));
            As[ar][ac+1] = __uint_as_float(f2tf32(ra[i].y));
            As[ar][ac+2] = __uint_as_float(f2tf32(ra[i].z));
            As[ar][ac+3] = __uint_as_float(f2tf32(ra[i].w));
            const int bk = idx >> 5, bc = (idx & 31) * 4;
            Bs[bc+0][bk] = __uint_as_float(f2tf32(rb[i].x));
            Bs[bc+1][bk] = __uint_as_float(f2tf32(rb[i].y));
            Bs[bc+2][bk] = __uint_as_float(f2tf32(rb[i].z));
            Bs[bc+3][bk] = __uint_as_float(f2tf32(rb[i].w));
        }
    };

    const int kTiles = K / 16;
    loadg(0);
    stores();
    __syncthreads();

    for (int kt = 0; kt < kTiles; kt++) {
        if (kt + 1 < kTiles) loadg((kt + 1) * 16);
#pragma unroll
        for (int k8 = 0; k8 < 16; k8 += 8) {
            uint32_t af[4][4], bf[4][2];
#pragma unroll
            for (int i = 0; i < 4; i++) {
                const int mb = wm * 64 + i * 16;
                af[i][0] = __float_as_uint(As[mb + g    ][k8 + t    ]);
                af[i][1] = __float_as_uint(As[mb + g + 8][k8 + t    ]);
                af[i][2] = __float_as_uint(As[mb + g    ][k8 + t + 4]);
                af[i][3] = __float_as_uint(As[mb + g + 8][k8 + t + 4]);
            }
#pragma unroll
            for (int j = 0; j < 4; j++) {
                const int nb = wn * 32 + j * 8;
                bf[j][0] = __float_as_uint(Bs[nb + g][k8 + t    ]);
                bf[j][1] = __float_as_uint(Bs[nb + g][k8 + t + 4]);
            }
#pragma unroll
            for (int i = 0; i < 4; i++)
#pragma unroll
                for (int j = 0; j < 4; j++)
                    mma_tf32(acc[i][j], af[i], bf[j]);
        }
        __syncthreads();
        if (kt + 1 < kTiles) {
            stores();
            __syncthreads();
        }
    }

#pragma unroll
    for (int i = 0; i < 4; i++) {
#pragma unroll
        for (int j = 0; j < 4; j++) {
            const int r = bm + wm * 64 + i * 16 + g;
            const int c = bn + wn * 32 + j * 8 + t * 2;
            float v0 = acc[i][j][0], v1 = acc[i][j][1];
            float v2 = acc[i][j][2], v3 = acc[i][j][3];
            if (EPI == 1) {
                v0 += resid[(size_t)r*N + c]       + cp[(size_t)r*(3*D_) + c*3 + 2];
                v1 += resid[(size_t)r*N + c + 1]   + cp[(size_t)r*(3*D_) + (c+1)*3 + 2];
                v2 += resid[(size_t)(r+8)*N + c]   + cp[(size_t)(r+8)*(3*D_) + c*3 + 2];
                v3 += resid[(size_t)(r+8)*N + c+1] + cp[(size_t)(r+8)*(3*D_) + (c+1)*3 + 2];
            }
            C[(size_t)r*N + c]         = v0;
            C[(size_t)r*N + c + 1]     = v1;
            C[(size_t)(r+8)*N + c]     = v2;
            C[(size_t)(r+8)*N + c + 1] = v3;
        }
    }
}

// ---------------- RMSNorm + AdaLN modulation ----------------
__global__ void modulate_kernel(const float* __restrict__ x,
                                const float* __restrict__ rms_scale,
                                const float* __restrict__ cp,
                                float* __restrict__ xm)
{
    const int row = blockIdx.x;
    const int tid = threadIdx.x;
    const float* xr = x + (size_t)row * D_;
    __shared__ float red[256];
    float s = 0.f;
    for (int d = tid; d < D_; d += 256) { float v = xr[d]; s += v*v; }
    red[tid] = s; __syncthreads();
    for (int o = 128; o > 0; o >>= 1) {
        if (tid < o) red[tid] += red[tid + o];
        __syncthreads();
    }
    const float rn = rsqrtf(red[0] / (float)D_ + EPS_);
    for (int d = tid; d < D_; d += 256) {
        const float scale = cp[(size_t)row*(3*D_) + 3*d    ];
        const float shift = cp[(size_t)row*(3*D_) + 3*d + 1];
        xm[(size_t)row*D_ + d] = xr[d]*rn*rms_scale[d]*(1.f + scale) + shift;
    }
}

// ---------------- RoPE + head split ----------------
__global__ void rope_split_kernel(const float* __restrict__ qkv,
                                  const float* __restrict__ pos,
                                  float* __restrict__ q, float* __restrict__ k,
                                  float* __restrict__ v)
{
    const int row = blockIdx.x;          // b*L + l
    const int b = row / L_, l = row % L_;
    const int tid = threadIdx.x;
    const float* qr = qkv + (size_t)row * 3 * D_;
    const float* pr = pos + (size_t)row * 2 * HD_;
    for (int e = tid; e < D_; e += 256) {
        const int h  = e & (H_-1);
        const int hd = e >> 4;
        const float qv = qr[3*e + 0];
        const float kv = qr[3*e + 1];
        const float vv = qr[3*e + 2];
        const int hd2 = (hd < 32) ? hd + 32 : hd - 32;
        const int e2  = hd2 * H_ + h;
        const float sgn = (hd < 32) ? -1.f : 1.f;
        const float q2 = qr[3*e2 + 0];
        const float k2 = qr[3*e2 + 1];
        const float sn = pr[2*hd];
        const float cs = pr[2*hd + 1];
        const size_t o = ((size_t)(b*H_ + h)*L_ + l)*HD_ + hd;
        q[o] = (qv*cs + sgn*q2*sn) * 0.125f;
        k[o] =  kv*cs + sgn*k2*sn;
        v[o] =  vv;
    }
}

// ---------------- attention: tf32 tensor-core flash, 64x64 tiles ----------------
// 128 threads = 4 warps; warp w owns Q rows [w*16, w*16+16).
// smem: sQ[64][68], sKP[64][68] (K tile, then reused for P), sV[64][72].
#define PADA 68
#define PADV 72
__global__ __launch_bounds__(128) void attn_mma_kernel(
    const float* __restrict__ q, const float* __restrict__ k,
    const float* __restrict__ v, float* __restrict__ out)
{
    extern __shared__ float sm[];
    float* sQ  = sm;                    // [64][68]
    float* sKP = sm + 64*PADA;          // [64][68]
    float* sV  = sm + 2*64*PADA;        // [64][72]

    const int qt = blockIdx.x;
    const int bh = blockIdx.y;
    const int b = bh >> 4, h = bh & 15;
    const int tid = threadIdx.x;
    const int lane = tid & 31, warp = tid >> 5;
    const int g = lane >> 2, t = lane & 3;    // quad row / quad lane
    const int wq = warp * 16;

    const float* qb = q + ((size_t)bh*L_ + qt*64)*HD_;
    const float* kb = k + (size_t)bh*L_*HD_;
    const float* vb = v + (size_t)bh*L_*HD_;

    // load Q tile (tf32-rounded)
    for (int i = tid; i < 64*16; i += 128) {
        const int r = i >> 4, c4 = (i & 15) * 4;
        float4 qv = *(const float4*)(qb + r*64 + c4);
        float* d = &sQ[r*PADA + c4];
        d[0] = __uint_as_float(f2tf32(qv.x));
        d[1] = __uint_as_float(f2tf32(qv.y));
        d[2] = __uint_as_float(f2tf32(qv.z));
        d[3] = __uint_as_float(f2tf32(qv.w));
    }

    float o[8][4];
#pragma unroll
    for (int j = 0; j < 8; j++)
#pragma unroll
        for (int e = 0; e < 4; e++) o[j][e] = 0.f;
    float m0 = -INFINITY, m1 = -INFINITY, l0 = 0.f, l1 = 0.f;

    for (int n0 = 0; n0 < L_; n0 += 64) {
        __syncthreads();   // prior iter done reading sKP(P)/sV; Q store visible
        // load K (tf32) and V (tf32) tiles
        for (int i = tid; i < 64*16; i += 128) {
            const int r = i >> 4, c4 = (i & 15) * 4;
            float4 kv = *(const float4*)(kb + (size_t)(n0+r)*64 + c4);
            float* dk = &sKP[r*PADA + c4];
            dk[0] = __uint_as_float(f2tf32(kv.x));
            dk[1] = __uint_as_float(f2tf32(kv.y));
            dk[2] = __uint_as_float(f2tf32(kv.z));
            dk[3] = __uint_as_float(f2tf32(kv.w));
            float4 vv = *(const float4*)(vb + (size_t)(n0+r)*64 + c4);
            float* dv = &sV[r*PADV + c4];
            dv[0] = __uint_as_float(f2tf32(vv.x));
            dv[1] = __uint_as_float(f2tf32(vv.y));
            dv[2] = __uint_as_float(f2tf32(vv.z));
            dv[3] = __uint_as_float(f2tf32(vv.w));
        }
        __syncthreads();

        // S = Q K^T  (warp: 16 rows x 64 cols)
        float s[8][4];
#pragma unroll
        for (int j = 0; j < 8; j++)
#pragma unroll
            for (int e = 0; e < 4; e++) s[j][e] = 0.f;
#pragma unroll
        for (int k8 = 0; k8 < 64; k8 += 8) {
            uint32_t a[4];
            a[0] = __float_as_uint(sQ[(wq+g  )*PADA + k8 + t    ]);
            a[1] = __float_as_uint(sQ[(wq+g+8)*PADA + k8 + t    ]);
            a[2] = __float_as_uint(sQ[(wq+g  )*PADA + k8 + t + 4]);
            a[3] = __float_as_uint(sQ[(wq+g+8)*PADA + k8 + t + 4]);
#pragma unroll
            for (int j = 0; j < 8; j++) {
                uint32_t bb[2];
                bb[0] = __float_as_uint(sKP[(j*8+g)*PADA + k8 + t    ]);
                bb[1] = __float_as_uint(sKP[(j*8+g)*PADA + k8 + t + 4]);
                mma_tf32(s[j], a, bb);
            }
        }
        __syncthreads();   // all warps done reading K from sKP

        // online softmax; row0 = wq+g (s[j][0..1]), row1 = wq+g+8 (s[j][2..3])
        float mx0 = -INFINITY, mx1 = -INFINITY;
#pragma unroll
        for (int j = 0; j < 8; j++) {
            mx0 = fmaxf(mx0, fmaxf(s[j][0], s[j][1]));
            mx1 = fmaxf(mx1, fmaxf(s[j][2], s[j][3]));
        }
        mx0 = fmaxf(mx0, __shfl_xor_sync(0xffffffffu, mx0, 1));
        mx0 = fmaxf(mx0, __shfl_xor_sync(0xffffffffu, mx0, 2));
        mx1 = fmaxf(mx1, __shfl_xor_sync(0xffffffffu, mx1, 1));
        mx1 = fmaxf(mx1, __shfl_xor_sync(0xffffffffu, mx1, 2));
        const float mn0 = fmaxf(m0, mx0), mn1 = fmaxf(m1, mx1);
        const float cr0 = __expf(m0 - mn0), cr1 = __expf(m1 - mn1);
        float rs0 = 0.f, rs1 = 0.f;
#pragma unroll
        for (int j = 0; j < 8; j++) {
            s[j][0] = __expf(s[j][0] - mn0);
            s[j][1] = __expf(s[j][1] - mn0);
            s[j][2] = __expf(s[j][2] - mn1);
            s[j][3] = __expf(s[j][3] - mn1);
            rs0 += s[j][0] + s[j][1];
            rs1 += s[j][2] + s[j][3];
        }
        rs0 += __shfl_xor_sync(0xffffffffu, rs0, 1);
        rs0 += __shfl_xor_sync(0xffffffffu, rs0, 2);
        rs1 += __shfl_xor_sync(0xffffffffu, rs1, 1);
        rs1 += __shfl_xor_sync(0xffffffffu, rs1, 2);
        l0 = l0*cr0 + rs0;  l1 = l1*cr1 + rs1;
        m0 = mn0;  m1 = mn1;
#pragma unroll
        for (int j = 0; j < 8; j++) {
            o[j][0] *= cr0; o[j][1] *= cr0;
            o[j][2] *= cr1; o[j][3] *= cr1;
        }

        // stage P (tf32) into sKP
#pragma unroll
        for (int j = 0; j < 8; j++) {
            float2 p0, p1;
            p0.x = __uint_as_float(f2tf32(s[j][0]));
            p0.y = __uint_as_float(f2tf32(s[j][1]));
            p1.x = __uint_as_float(f2tf32(s[j][2]));
            p1.y = __uint_as_float(f2tf32(s[j][3]));
            *(float2*)&sKP[(wq+g  )*PADA + j*8 + 2*t] = p0;
            *(float2*)&sKP[(wq+g+8)*PADA + j*8 + 2*t] = p1;
        }
        __syncthreads();

        // O += P V
#pragma unroll
        for (int k8 = 0; k8 < 64; k8 += 8) {
            uint32_t a[4];
            a[0] = __float_as_uint(sKP[(wq+g  )*PADA + k8 + t    ]);
            a[1] = __float_as_uint(sKP[(wq+g+8)*PADA + k8 + t    ]);
            a[2] = __float_as_uint(sKP[(wq+g  )*PADA + k8 + t + 4]);
            a[3] = __float_as_uint(sKP[(wq+g+8)*PADA + k8 + t + 4]);
#pragma unroll
            for (int j = 0; j < 8; j++) {
                uint32_t bb[2];
                bb[0] = __float_as_uint(sV[(k8+t  )*PADV + j*8 + g]);
                bb[1] = __float_as_uint(sV[(k8+t+4)*PADV + j*8 + g]);
                mma_tf32(o[j], a, bb);
            }
        }
    }

    // epilogue: write (b, l, h*64+col), scaled by 1/l
    const float inv0 = 1.f / l0, inv1 = 1.f / l1;
    const int r0 = qt*64 + wq + g, r1 = r0 + 8;
#pragma unroll
    for (int j = 0; j < 8; j++) {
        const int c = h*64 + j*8 + 2*t;
        float2 w0, w1;
        w0.x = o[j][0]*inv0; w0.y = o[j][1]*inv0;
        w1.x = o[j][2]*inv1; w1.y = o[j][3]*inv1;
        *(float2*)&out[((size_t)(b*L_ + r0))*D_ + c] = w0;
        *(float2*)&out[((size_t)(b*L_ + r1))*D_ + c] = w1;
    }
}

// ---------------- launch ----------------
extern "C" void kernel_launch(void* const* d_in, const int* in_sizes, int n_in,
                              void* d_out, int out_size)
{
    const float* x         = (const float*)d_in[0];
    const float* cond      = (const float*)d_in[1];
    const float* pos       = (const float*)d_in[2];
    const float* rms_scale = (const float*)d_in[3];
    const float* W_cond    = (const float*)d_in[4];
    const float* W_qkv     = (const float*)d_in[5];
    const float* W_out     = (const float*)d_in[6];
    float* out = (float*)d_out;

    float *cp, *xm, *qkv, *qb, *kb, *vb, *ao;
    cudaGetSymbolAddress((void**)&cp,  g_cp);
    cudaGetSymbolAddress((void**)&xm,  g_xm);
    cudaGetSymbolAddress((void**)&qkv, g_qkv);
    cudaGetSymbolAddress((void**)&qb,  g_q);
    cudaGetSymbolAddress((void**)&kb,  g_k);
    cudaGetSymbolAddress((void**)&vb,  g_v);
    cudaGetSymbolAddress((void**)&ao,  g_ao);

    const int smem_attn = (2*64*PADA + 64*PADV) * (int)sizeof(float);  // 53,248 B
    cudaFuncSetAttribute(attn_mma_kernel, cudaFuncAttributeMaxDynamicSharedMemorySize, smem_attn);

    // 1) cond projection
    {
        dim3 g(3*D_/128, ROWS_/128);
        gemm_tf32<0><<<g, 256>>>(cond, W_cond, cp, ROWS_, 3*D_, D_, nullptr, nullptr);
    }
    // 2) RMSNorm + modulation
    modulate_kernel<<<ROWS_, 256>>>(x, rms_scale, cp, xm);
    // 3) QKV projection
    {
        dim3 g(3*D_/128, ROWS_/128);
        gemm_tf32<0><<<g, 256>>>(xm, W_qkv, qkv, ROWS_, 3*D_, D_, nullptr, nullptr);
    }
    // 4) RoPE + head split
    rope_split_kernel<<<ROWS_, 256>>>(qkv, pos, qb, kb, vb);
    // 5) attention (tensor cores)
    {
        dim3 g(L_/64, B_*H_);
        attn_mma_kernel<<<g, 128, smem_attn>>>(qb, kb, vb, ao);
    }
    // 6) output projection + residual + gate
    {
        dim3 g(D_/128, ROWS_/128);
        gemm_tf32<1><<<g, 256>>>(ao, W_out, out, ROWS_, D_, D_, x, cp);
    }
}

// round 6
// speedup vs baseline: 3.0701x; 1.6224x over previous
#include <cuda_runtime.h>
#include <stdint.h>
#include <math.h>

#define B_  2
#define L_  2048
#define D_  1024
#define H_  16
#define HD_ 64
#define ROWS_ (B_*L_)          // 4096
#define EPS_ 1e-6f

// ---------------- scratch (no allocations allowed) ----------------
__device__ float g_cp [ROWS_*3*D_];   // cond proj: (row, d*3+comp)
__device__ float g_xm [ROWS_*D_];     // modulated normed x
__device__ float g_qkv[ROWS_*3*D_];   // qkv proj
__device__ float g_q  [ROWS_*D_];     // (b,h,l,hd), q pre-scaled by 1/8
__device__ float g_k  [ROWS_*D_];
__device__ float g_v  [ROWS_*D_];
__device__ float g_ao [ROWS_*D_];     // attention output (b,l, h*64+hd)

// ---------------- tf32 helpers ----------------
__device__ __forceinline__ uint32_t f2tf32(float f) {
    uint32_t r;
    asm("cvt.rna.tf32.f32 %0, %1;" : "=r"(r) : "f"(f));
    return r;
}

__device__ __forceinline__ void mma_tf32(float* c, const uint32_t* a, const uint32_t* b) {
    asm volatile(
        "mma.sync.aligned.m16n8k8.row.col.f32.tf32.tf32.f32 "
        "{%0,%1,%2,%3}, {%4,%5,%6,%7}, {%8,%9}, {%0,%1,%2,%3};"
        : "+f"(c[0]), "+f"(c[1]), "+f"(c[2]), "+f"(c[3])
        : "r"(a[0]), "r"(a[1]), "r"(a[2]), "r"(a[3]), "r"(b[0]), "r"(b[1]));
}

__device__ __forceinline__ void cp_async16(void* smem_dst, const void* gmem_src) {
    uint32_t s = (uint32_t)__cvta_generic_to_shared(smem_dst);
    asm volatile("cp.async.cg.shared.global [%0], [%1], 16;\n" :: "r"(s), "l"(gmem_src));
}
__device__ __forceinline__ void cp_commit() {
    asm volatile("cp.async.commit_group;\n");
}
template<int N>
__device__ __forceinline__ void cp_wait() {
    asm volatile("cp.async.wait_group %0;\n" :: "n"(N));
}

// ---------------- tf32 GEMM: 128x128 tile, BK=32, 3-stage cp.async pipeline ----
// C[M,N] = A[M,K] @ B[K,N], row-major. EPI=1: += resid[row,col] + cp[row,col*3+2]
// 256 threads = 8 warps in 2(M) x 4(N); warp tile 64x32 = 4x4 frags of m16n8k8.
#define GP_STAGES 3
#define GP_APAD 36
#define GP_BPAD 132
#define GP_ASZ (128*GP_APAD)
#define GP_BSZ (32*GP_BPAD)
#define GP_SMEM (GP_STAGES*(GP_ASZ+GP_BSZ)*(int)sizeof(float))   // 105,984 B

template<int EPI>
__global__ __launch_bounds__(256) void gemm_pipe(
    const float* __restrict__ A, const float* __restrict__ Bm,
    float* __restrict__ C, int M, int N, int K,
    const float* __restrict__ resid, const float* __restrict__ cp)
{
    extern __shared__ float smp[];
    float* AsBase = smp;
    float* BsBase = smp + GP_STAGES*GP_ASZ;

    const int tid  = threadIdx.x;
    const int lane = tid & 31;
    const int warp = tid >> 5;
    const int wm = warp & 1;        // 0..1  (64-row slab)
    const int wn = warp >> 1;       // 0..3  (32-col slab)
    const int bm = blockIdx.y * 128, bn = blockIdx.x * 128;
    const int g = lane >> 2;        // 0..7
    const int t = lane & 3;         // 0..3

    float acc[4][4][4];
#pragma unroll
    for (int i = 0; i < 4; i++)
#pragma unroll
        for (int j = 0; j < 4; j++)
#pragma unroll
            for (int e = 0; e < 4; e++) acc[i][j][e] = 0.f;

    const int kTiles = K / 32;

    auto issue = [&](int kt, int s) {
        const int k0 = kt * 32;
        float* as = AsBase + s * GP_ASZ;
        float* bs = BsBase + s * GP_BSZ;
#pragma unroll
        for (int i = 0; i < 4; i++) {
            const int idx = tid + i * 256;          // 0..1023
            const int ar = idx >> 3, ac = (idx & 7) * 4;     // A: 128x32
            cp_async16(&as[ar*GP_APAD + ac], A + (size_t)(bm + ar) * K + k0 + ac);
            const int br = idx >> 5, bc = (idx & 31) * 4;    // B: 32x128
            cp_async16(&bs[br*GP_BPAD + bc], Bm + (size_t)(k0 + br) * N + bn + bc);
        }
    };

#pragma unroll
    for (int s = 0; s < GP_STAGES; s++) {
        if (s < kTiles) issue(s, s);
        cp_commit();
    }

    for (int kt = 0; kt < kTiles; kt++) {
        cp_wait<GP_STAGES-1>();
        __syncthreads();
        const int s = kt % GP_STAGES;
        const float* as = AsBase + s * GP_ASZ;
        const float* bs = BsBase + s * GP_BSZ;
#pragma unroll
        for (int k8 = 0; k8 < 32; k8 += 8) {
            uint32_t af[4][4], bf[4][2];
#pragma unroll
            for (int i = 0; i < 4; i++) {
                const int mb = wm * 64 + i * 16;
                af[i][0] = f2tf32(as[(mb + g    )*GP_APAD + k8 + t    ]);
                af[i][1] = f2tf32(as[(mb + g + 8)*GP_APAD + k8 + t    ]);
                af[i][2] = f2tf32(as[(mb + g    )*GP_APAD + k8 + t + 4]);
                af[i][3] = f2tf32(as[(mb + g + 8)*GP_APAD + k8 + t + 4]);
            }
#pragma unroll
            for (int j = 0; j < 4; j++) {
                const int nb = wn * 32 + j * 8;
                bf[j][0] = f2tf32(bs[(k8 + t    )*GP_BPAD + nb + g]);
                bf[j][1] = f2tf32(bs[(k8 + t + 4)*GP_BPAD + nb + g]);
            }
#pragma unroll
            for (int i = 0; i < 4; i++)
#pragma unroll
                for (int j = 0; j < 4; j++)
                    mma_tf32(acc[i][j], af[i], bf[j]);
        }
        __syncthreads();
        if (kt + GP_STAGES < kTiles) issue(kt + GP_STAGES, s);
        cp_commit();
    }

    // epilogue: c0,c1 at (row, col/col+1); c2,c3 at row+8
#pragma unroll
    for (int i = 0; i < 4; i++) {
#pragma unroll
        for (int j = 0; j < 4; j++) {
            const int r = bm + wm * 64 + i * 16 + g;
            const int c = bn + wn * 32 + j * 8 + t * 2;
            float v0 = acc[i][j][0], v1 = acc[i][j][1];
            float v2 = acc[i][j][2], v3 = acc[i][j][3];
            if (EPI == 1) {
                v0 += resid[(size_t)r*N + c]       + cp[(size_t)r*(3*D_) + c*3 + 2];
                v1 += resid[(size_t)r*N + c + 1]   + cp[(size_t)r*(3*D_) + (c+1)*3 + 2];
                v2 += resid[(size_t)(r+8)*N + c]   + cp[(size_t)(r+8)*(3*D_) + c*3 + 2];
                v3 += resid[(size_t)(r+8)*N + c+1] + cp[(size_t)(r+8)*(3*D_) + (c+1)*3 + 2];
            }
            C[(size_t)r*N + c]         = v0;
            C[(size_t)r*N + c + 1]     = v1;
            C[(size_t)(r+8)*N + c]     = v2;
            C[(size_t)(r+8)*N + c + 1] = v3;
        }
    }
}

// ---------------- RMSNorm + AdaLN modulation ----------------
__global__ void modulate_kernel(const float* __restrict__ x,
                                const float* __restrict__ rms_scale,
                                const float* __restrict__ cp,
                                float* __restrict__ xm)
{
    const int row = blockIdx.x;
    const int tid = threadIdx.x;
    const float* xr = x + (size_t)row * D_;
    __shared__ float red[256];
    float s = 0.f;
    for (int d = tid; d < D_; d += 256) { float v = xr[d]; s += v*v; }
    red[tid] = s; __syncthreads();
    for (int o = 128; o > 0; o >>= 1) {
        if (tid < o) red[tid] += red[tid + o];
        __syncthreads();
    }
    const float rn = rsqrtf(red[0] / (float)D_ + EPS_);
    for (int d = tid; d < D_; d += 256) {
        const float scale = cp[(size_t)row*(3*D_) + 3*d    ];
        const float shift = cp[(size_t)row*(3*D_) + 3*d + 1];
        xm[(size_t)row*D_ + d] = xr[d]*rn*rms_scale[d]*(1.f + scale) + shift;
    }
}

// ---------------- RoPE + head split ----------------
__global__ void rope_split_kernel(const float* __restrict__ qkv,
                                  const float* __restrict__ pos,
                                  float* __restrict__ q, float* __restrict__ k,
                                  float* __restrict__ v)
{
    const int row = blockIdx.x;          // b*L + l
    const int b = row / L_, l = row % L_;
    const int tid = threadIdx.x;
    const float* qr = qkv + (size_t)row * 3 * D_;
    const float* pr = pos + (size_t)row * 2 * HD_;
    for (int e = tid; e < D_; e += 256) {
        const int h  = e & (H_-1);
        const int hd = e >> 4;
        const float qv = qr[3*e + 0];
        const float kv = qr[3*e + 1];
        const float vv = qr[3*e + 2];
        const int hd2 = (hd < 32) ? hd + 32 : hd - 32;
        const int e2  = hd2 * H_ + h;
        const float sgn = (hd < 32) ? -1.f : 1.f;
        const float q2 = qr[3*e2 + 0];
        const float k2 = qr[3*e2 + 1];
        const float sn = pr[2*hd];
        const float cs = pr[2*hd + 1];
        const size_t o = ((size_t)(b*H_ + h)*L_ + l)*HD_ + hd;
        q[o] = (qv*cs + sgn*q2*sn) * 0.125f;
        k[o] =  kv*cs + sgn*k2*sn;
        v[o] =  vv;
    }
}

// ---------------- attention: tf32 tensor-core flash, 64x64 tiles ----------------
#define PADA 68
#define PADV 72
__global__ __launch_bounds__(128) void attn_mma_kernel(
    const float* __restrict__ q, const float* __restrict__ k,
    const float* __restrict__ v, float* __restrict__ out)
{
    extern __shared__ float sm[];
    float* sQ  = sm;                    // [64][68]
    float* sKP = sm + 64*PADA;          // [64][68]
    float* sV  = sm + 2*64*PADA;        // [64][72]

    const int qt = blockIdx.x;
    const int bh = blockIdx.y;
    const int b = bh >> 4, h = bh & 15;
    const int tid = threadIdx.x;
    const int lane = tid & 31, warp = tid >> 5;
    const int g = lane >> 2, t = lane & 3;
    const int wq = warp * 16;

    const float* qb = q + ((size_t)bh*L_ + qt*64)*HD_;
    const float* kb = k + (size_t)bh*L_*HD_;
    const float* vb = v + (size_t)bh*L_*HD_;

    for (int i = tid; i < 64*16; i += 128) {
        const int r = i >> 4, c4 = (i & 15) * 4;
        float4 qv = *(const float4*)(qb + r*64 + c4);
        float* d = &sQ[r*PADA + c4];
        d[0] = __uint_as_float(f2tf32(qv.x));
        d[1] = __uint_as_float(f2tf32(qv.y));
        d[2] = __uint_as_float(f2tf32(qv.z));
        d[3] = __uint_as_float(f2tf32(qv.w));
    }

    float o[8][4];
#pragma unroll
    for (int j = 0; j < 8; j++)
#pragma unroll
        for (int e = 0; e < 4; e++) o[j][e] = 0.f;
    float m0 = -INFINITY, m1 = -INFINITY, l0 = 0.f, l1 = 0.f;

    for (int n0 = 0; n0 < L_; n0 += 64) {
        __syncthreads();
        for (int i = tid; i < 64*16; i += 128) {
            const int r = i >> 4, c4 = (i & 15) * 4;
            float4 kv = *(const float4*)(kb + (size_t)(n0+r)*64 + c4);
            float* dk = &sKP[r*PADA + c4];
            dk[0] = __uint_as_float(f2tf32(kv.x));
            dk[1] = __uint_as_float(f2tf32(kv.y));
            dk[2] = __uint_as_float(f2tf32(kv.z));
            dk[3] = __uint_as_float(f2tf32(kv.w));
            float4 vv = *(const float4*)(vb + (size_t)(n0+r)*64 + c4);
            float* dv = &sV[r*PADV + c4];
            dv[0] = __uint_as_float(f2tf32(vv.x));
            dv[1] = __uint_as_float(f2tf32(vv.y));
            dv[2] = __uint_as_float(f2tf32(vv.z));
            dv[3] = __uint_as_float(f2tf32(vv.w));
        }
        __syncthreads();

        float s[8][4];
#pragma unroll
        for (int j = 0; j < 8; j++)
#pragma unroll
            for (int e = 0; e < 4; e++) s[j][e] = 0.f;
#pragma unroll
        for (int k8 = 0; k8 < 64; k8 += 8) {
            uint32_t a[4];
            a[0] = __float_as_uint(sQ[(wq+g  )*PADA + k8 + t    ]);
            a[1] = __float_as_uint(sQ[(wq+g+8)*PADA + k8 + t    ]);
            a[2] = __float_as_uint(sQ[(wq+g  )*PADA + k8 + t + 4]);
            a[3] = __float_as_uint(sQ[(wq+g+8)*PADA + k8 + t + 4]);
#pragma unroll
            for (int j = 0; j < 8; j++) {
                uint32_t bb[2];
                bb[0] = __float_as_uint(sKP[(j*8+g)*PADA + k8 + t    ]);
                bb[1] = __float_as_uint(sKP[(j*8+g)*PADA + k8 + t + 4]);
                mma_tf32(s[j], a, bb);
            }
        }
        __syncthreads();

        float mx0 = -INFINITY, mx1 = -INFINITY;
#pragma unroll
        for (int j = 0; j < 8; j++) {
            mx0 = fmaxf(mx0, fmaxf(s[j][0], s[j][1]));
            mx1 = fmaxf(mx1, fmaxf(s[j][2], s[j][3]));
        }
        mx0 = fmaxf(mx0, __shfl_xor_sync(0xffffffffu, mx0, 1));
        mx0 = fmaxf(mx0, __shfl_xor_sync(0xffffffffu, mx0, 2));
        mx1 = fmaxf(mx1, __shfl_xor_sync(0xffffffffu, mx1, 1));
        mx1 = fmaxf(mx1, __shfl_xor_sync(0xffffffffu, mx1, 2));
        const float mn0 = fmaxf(m0, mx0), mn1 = fmaxf(m1, mx1);
        const float cr0 = __expf(m0 - mn0), cr1 = __expf(m1 - mn1);
        float rs0 = 0.f, rs1 = 0.f;
#pragma unroll
        for (int j = 0; j < 8; j++) {
            s[j][0] = __expf(s[j][0] - mn0);
            s[j][1] = __expf(s[j][1] - mn0);
            s[j][2] = __expf(s[j][2] - mn1);
            s[j][3] = __expf(s[j][3] - mn1);
            rs0 += s[j][0] + s[j][1];
            rs1 += s[j][2] + s[j][3];
        }
        rs0 += __shfl_xor_sync(0xffffffffu, rs0, 1);
        rs0 += __shfl_xor_sync(0xffffffffu, rs0, 2);
        rs1 += __shfl_xor_sync(0xffffffffu, rs1, 1);
        rs1 += __shfl_xor_sync(0xffffffffu, rs1, 2);
        l0 = l0*cr0 + rs0;  l1 = l1*cr1 + rs1;
        m0 = mn0;  m1 = mn1;
#pragma unroll
        for (int j = 0; j < 8; j++) {
            o[j][0] *= cr0; o[j][1] *= cr0;
            o[j][2] *= cr1; o[j][3] *= cr1;
        }

#pragma unroll
        for (int j = 0; j < 8; j++) {
            float2 p0, p1;
            p0.x = __uint_as_float(f2tf32(s[j][0]));
            p0.y = __uint_as_float(f2tf32(s[j][1]));
            p1.x = __uint_as_float(f2tf32(s[j][2]));
            p1.y = __uint_as_float(f2tf32(s[j][3]));
            *(float2*)&sKP[(wq+g  )*PADA + j*8 + 2*t] = p0;
            *(float2*)&sKP[(wq+g+8)*PADA + j*8 + 2*t] = p1;
        }
        __syncthreads();

#pragma unroll
        for (int k8 = 0; k8 < 64; k8 += 8) {
            uint32_t a[4];
            a[0] = __float_as_uint(sKP[(wq+g  )*PADA + k8 + t    ]);
            a[1] = __float_as_uint(sKP[(wq+g+8)*PADA + k8 + t    ]);
            a[2] = __float_as_uint(sKP[(wq+g  )*PADA + k8 + t + 4]);
            a[3] = __float_as_uint(sKP[(wq+g+8)*PADA + k8 + t + 4]);
#pragma unroll
            for (int j = 0; j < 8; j++) {
                uint32_t bb[2];
                bb[0] = __float_as_uint(sV[(k8+t  )*PADV + j*8 + g]);
                bb[1] = __float_as_uint(sV[(k8+t+4)*PADV + j*8 + g]);
                mma_tf32(o[j], a, bb);
            }
        }
    }

    const float inv0 = 1.f / l0, inv1 = 1.f / l1;
    const int r0 = qt*64 + wq + g, r1 = r0 + 8;
#pragma unroll
    for (int j = 0; j < 8; j++) {
        const int c = h*64 + j*8 + 2*t;
        float2 w0, w1;
        w0.x = o[j][0]*inv0; w0.y = o[j][1]*inv0;
        w1.x = o[j][2]*inv1; w1.y = o[j][3]*inv1;
        *(float2*)&out[((size_t)(b*L_ + r0))*D_ + c] = w0;
        *(float2*)&out[((size_t)(b*L_ + r1))*D_ + c] = w1;
    }
}

// ---------------- launch ----------------
extern "C" void kernel_launch(void* const* d_in, const int* in_sizes, int n_in,
                              void* d_out, int out_size)
{
    const float* x         = (const float*)d_in[0];
    const float* cond      = (const float*)d_in[1];
    const float* pos       = (const float*)d_in[2];
    const float* rms_scale = (const float*)d_in[3];
    const float* W_cond    = (const float*)d_in[4];
    const float* W_qkv     = (const float*)d_in[5];
    const float* W_out     = (const float*)d_in[6];
    float* out = (float*)d_out;

    float *cp, *xm, *qkv, *qb, *kb, *vb, *ao;
    cudaGetSymbolAddress((void**)&cp,  g_cp);
    cudaGetSymbolAddress((void**)&xm,  g_xm);
    cudaGetSymbolAddress((void**)&qkv, g_qkv);
    cudaGetSymbolAddress((void**)&qb,  g_q);
    cudaGetSymbolAddress((void**)&kb,  g_k);
    cudaGetSymbolAddress((void**)&vb,  g_v);
    cudaGetSymbolAddress((void**)&ao,  g_ao);

    const int smem_attn = (2*64*PADA + 64*PADV) * (int)sizeof(float);  // 53,248 B
    cudaFuncSetAttribute(attn_mma_kernel, cudaFuncAttributeMaxDynamicSharedMemorySize, smem_attn);
    cudaFuncSetAttribute(gemm_pipe<0>, cudaFuncAttributeMaxDynamicSharedMemorySize, GP_SMEM);
    cudaFuncSetAttribute(gemm_pipe<1>, cudaFuncAttributeMaxDynamicSharedMemorySize, GP_SMEM);

    // 1) cond projection
    {
        dim3 g(3*D_/128, ROWS_/128);
        gemm_pipe<0><<<g, 256, GP_SMEM>>>(cond, W_cond, cp, ROWS_, 3*D_, D_, nullptr, nullptr);
    }
    // 2) RMSNorm + modulation
    modulate_kernel<<<ROWS_, 256>>>(x, rms_scale, cp, xm);
    // 3) QKV projection
    {
        dim3 g(3*D_/128, ROWS_/128);
        gemm_pipe<0><<<g, 256, GP_SMEM>>>(xm, W_qkv, qkv, ROWS_, 3*D_, D_, nullptr, nullptr);
    }
    // 4) RoPE + head split
    rope_split_kernel<<<ROWS_, 256>>>(qkv, pos, qb, kb, vb);
    // 5) attention (tensor cores)
    {
        dim3 g(L_/64, B_*H_);
        attn_mma_kernel<<<g, 128, smem_attn>>>(qb, kb, vb, ao);
    }
    // 6) output projection + residual + gate
    {
        dim3 g(D_/128, ROWS_/128);
        gemm_pipe<1><<<g, 256, GP_SMEM>>>(ao, W_out, out, ROWS_, D_, D_, x, cp);
    }
}